// round 15
// baseline (speedup 1.0000x reference)
#include <cuda_runtime.h>
#include <cuda_fp16.h>
#include <cstdint>

#define BATCH 4096
#define S_SZ  200
#define D_SZ  256
#define NSPL  5             // fifths per batch: m-tiles 3/3/3/2/2

// ---- K_score dynamic SMEM word map (max NMT=3) ----
#define XH_W     0          // 3*2048 words: X_hi fp16 fragments
#define XL_W     6144       // X_lo fragments
#define SC_W     12288      // 256 f32 combined bias
#define SCORE_W  12544      // 48 f32 row sums / exp values
#define SRED_W   12592      // 20 f32 reduction scratch
#define SMEM_WORDS 12612
#define SMEM_BYTES (SMEM_WORDS * 4)

__device__ float g_catep[BATCH * D_SZ];
__device__ int   g_mask_mode;                 // 0=u8, 1=i32, 2=f32
__device__ uint4 g_w1pk[32 * 16 * 32];        // 256 KB packed fp16 W hi/lo fragments
__device__ float g_pm[BATCH * NSPL];          // per-fifth local max
__device__ float g_pl[BATCH * NSPL];          // per-fifth local exp-sum
__device__ float g_pp[BATCH * NSPL * D_SZ];   // per-fifth unnormalized pooled partials

__device__ __forceinline__ unsigned pack_hf2(float lo, float hi) {
    unsigned r;
    asm("cvt.rn.f16x2.f32 %0, %1, %2;" : "=r"(r) : "f"(hi), "f"(lo));
    return r;
}
__device__ __forceinline__ float hf_lo(unsigned w) { return __half2float(__ushort_as_half((unsigned short)(w & 0xFFFFu))); }
__device__ __forceinline__ float hf_hi(unsigned w) { return __half2float(__ushort_as_half((unsigned short)(w >> 16))); }
__device__ __forceinline__ float sigf(float x) { return __fdividef(1.0f, 1.0f + __expf(-x)); }

#define MMAF16(d, a0, a1, a2, a3, b0, b1)                                     \
    asm volatile("mma.sync.aligned.m16n8k16.row.col.f32.f16.f16.f32 "         \
                 "{%0,%1,%2,%3}, {%4,%5,%6,%7}, {%8,%9}, {%0,%1,%2,%3};"      \
                 : "+f"(d[0]), "+f"(d[1]), "+f"(d[2]), "+f"(d[3])             \
                 : "r"(a0), "r"(a1), "r"(a2), "r"(a3), "r"(b0), "r"(b1))

// ---------------------------------------------------------------------------
// Prep: blocks 0..255 = catep GEMM (fp32 exact), 256 = W1 fp16 hi/lo fragment
// pack, 257 = mask dtype detection.  (unchanged from the 928us baseline)
// ---------------------------------------------------------------------------
__global__ void prep_kernel(const float* __restrict__ cate,
                            const float* __restrict__ W2,
                            const float* __restrict__ b2,
                            const float* __restrict__ W1,
                            const unsigned* __restrict__ mw) {
    __shared__ float sm[16 * 256];
    __shared__ int   fl[2];
    const int blk = blockIdx.x, tid = threadIdx.x;

    if (blk < 256) {
        const int bbase = blk * 16;
        #pragma unroll
        for (int i = 0; i < 16; i++)
            sm[i * 256 + tid] = cate[(size_t)(bbase + i) * 256 + tid];
        __syncthreads();

        float acc[16];
        #pragma unroll
        for (int r = 0; r < 16; r++) acc[r] = 0.0f;
        const float4* w2row = (const float4*)(W2 + (size_t)tid * 256);
        #pragma unroll 8
        for (int k4 = 0; k4 < 64; k4++) {
            const float4 w = w2row[k4];
            #pragma unroll
            for (int r = 0; r < 16; r++) {
                const float4 s4 = *(const float4*)(sm + r * 256 + k4 * 4);
                acc[r] += s4.x * w.x + s4.y * w.y + s4.z * w.z + s4.w * w.w;
            }
        }
        const float bias = b2[tid];
        #pragma unroll
        for (int r = 0; r < 16; r++)
            g_catep[(size_t)(bbase + r) * 256 + tid] = acc[r] + bias;
    } else if (blk == 256) {
        // entry e = (ntg*16 + kt)*32 + lane ; lane = qr*4 + qc
        for (int e = tid; e < 32 * 16 * 32; e += 256) {
            const int ntg = e >> 9, kt = (e >> 5) & 15, lane = e & 31;
            const int qr = lane >> 2, qc = lane & 3;
            const float* src = W1 + (size_t)(ntg * 8 + qr) * 256 + kt * 16 + 2 * qc;
            const float w0 = src[0], w1v = src[1], w8 = src[8], w9 = src[9];
            const unsigned h0 = pack_hf2(w0, w1v);
            const unsigned h1 = pack_hf2(w8, w9);
            const float2 f0 = __half22float2(*(const __half2*)&h0);
            const float2 f1 = __half22float2(*(const __half2*)&h1);
            const unsigned l0 = pack_hf2(w0 - f0.x, w1v - f0.y);
            const unsigned l1 = pack_hf2(w8 - f1.x, w9 - f1.y);
            g_w1pk[e] = make_uint4(h0, h1, l0, l1);
        }
    } else {
        if (tid == 0) { fl[0] = 0; fl[1] = 0; }
        __syncthreads();
        int lF = 0, lU = 0;
        for (int i = tid; i < 4096; i += 256) {
            const unsigned v = mw[i];
            if (v == 0x3F800000u) lF = 1;
            if (v & 0xFFFFFF00u)  lU = 1;
        }
        if (lF) fl[0] = 1;
        if (lU) fl[1] = 1;
        __syncthreads();
        if (tid == 0) g_mask_mode = fl[0] ? 2 : (fl[1] ? 0 : 1);
    }
}

// ---------------------------------------------------------------------------
// Score body: direct load + fp16 hi/lo split (R11 structure), balanced GEMM
// (warp = one 32-wide n-strip, all NMT m-tiles), local masked softmax +
// unnormalized pooled partial (flash-style two-level softmax).
// ---------------------------------------------------------------------------
template <int NMT>
__device__ __forceinline__ void score_body(const float* __restrict__ seq,
                                           const void*  __restrict__ maskp,
                                           const float* __restrict__ b1,
                                           int b, int fifth, int r0) {
    extern __shared__ unsigned sw[];
    const int nr  = NMT * 16;
    const int tid = threadIdx.x, warp = tid >> 5, lane = tid & 31;
    const int qr = lane >> 2, qc = lane & 3;

    float* sC     = (float*)(sw + SC_W);
    float* sScore = (float*)(sw + SCORE_W);
    float* sRed   = (float*)(sw + SRED_W);

    // early mask load (rows >= S_SZ are padding -> masked)
    bool mk = true;
    if (tid < nr) {
        const int s = r0 + tid;
        if (s < S_SZ) {
            const size_t mi = (size_t)b * S_SZ + s;
            const int mode = g_mask_mode;
            if (mode == 0)      mk = ((const unsigned char*)maskp)[mi] != 0;
            else if (mode == 1) mk = ((const int*)maskp)[mi] != 0;
            else                mk = ((const float*)maskp)[mi] != 0.0f;
        }
    }

    sC[tid] = g_catep[(size_t)b * 256 + tid] + b1[tid];
    if (tid < 48) sScore[tid] = 0.0f;
    __syncthreads();

    // ---- P1: load rows [r0, r0+nr) + fp16 hi/lo split, fragment order ----
    {
        const float4* gsrc = (const float4*)(seq + (size_t)b * S_SZ * D_SZ);
        const int nidx = nr * 64;
        for (int idx = tid; idx < nidx; idx += 256) {
            const int lr = idx >> 6, c4 = idx & 63;
            const int g = r0 + lr;
            float4 v = make_float4(0.f, 0.f, 0.f, 0.f);
            if (g < S_SZ) v = gsrc[g * 64 + c4];
            const unsigned h01 = pack_hf2(v.x, v.y);
            const unsigned h23 = pack_hf2(v.z, v.w);
            const float2 f01 = __half22float2(*(const __half2*)&h01);
            const float2 f23 = __half22float2(*(const __half2*)&h23);
            const unsigned l01 = pack_hf2(v.x - f01.x, v.y - f01.y);
            const unsigned l23 = pack_hf2(v.z - f23.x, v.w - f23.y);
            const int cp = 2 * c4, rr = cp & 7;
            const int r16 = lr & 15;
            const int widx = (lr >> 4) * 2048 + (cp >> 3) * 128
                           + (r16 & 7) * 16 + (rr & 3) * 4 + (rr >> 2) * 2 + (r16 >> 3);
            sw[XH_W + widx]     = h01;
            sw[XH_W + widx + 4] = h23;
            sw[XL_W + widx]     = l01;
            sw[XL_W + widx + 4] = l23;
        }
    }
    __syncthreads();

    // ---- P2: balanced GEMM, warp n-strip [warp*32, warp*32+32) ----
    {
        const int n0   = warp * 32;
        const int ntg0 = n0 >> 3;

        float acc[NMT][4][4];
        #pragma unroll
        for (int mt = 0; mt < NMT; mt++)
            #pragma unroll
            for (int j = 0; j < 4; j++)
                #pragma unroll
                for (int i = 0; i < 4; i++) acc[mt][j][i] = 0.0f;

        uint4 wq[4];
        #pragma unroll
        for (int j = 0; j < 4; j++)
            wq[j] = g_w1pk[(size_t)((ntg0 + j) * 16) * 32 + lane];

        #pragma unroll 1
        for (int kt = 0; kt < 16; kt++) {
            uint4 w[4];
            #pragma unroll
            for (int j = 0; j < 4; j++) w[j] = wq[j];
            if (kt < 15) {
                #pragma unroll
                for (int j = 0; j < 4; j++)
                    wq[j] = g_w1pk[(size_t)((ntg0 + j) * 16 + kt + 1) * 32 + lane];
            }
            const unsigned abase = kt * 128 + lane * 4;
            #pragma unroll
            for (int mt = 0; mt < NMT; mt++) {
                const uint4 ah = *(const uint4*)(sw + XH_W + mt * 2048 + abase);
                const uint4 al = *(const uint4*)(sw + XL_W + mt * 2048 + abase);
                #pragma unroll
                for (int j = 0; j < 4; j++)
                    MMAF16(acc[mt][j], ah.x, ah.y, ah.z, ah.w, w[j].x, w[j].y);
                #pragma unroll
                for (int j = 0; j < 4; j++)
                    MMAF16(acc[mt][j], al.x, al.y, al.z, al.w, w[j].x, w[j].y);
                #pragma unroll
                for (int j = 0; j < 4; j++)
                    MMAF16(acc[mt][j], ah.x, ah.y, ah.z, ah.w, w[j].z, w[j].w);
            }
        }

        float b0[4], b1v[4];
        #pragma unroll
        for (int j = 0; j < 4; j++) {
            b0[j]  = sC[n0 + j * 8 + 2 * qc];
            b1v[j] = sC[n0 + j * 8 + 2 * qc + 1];
        }
        #pragma unroll
        for (int mt = 0; mt < NMT; mt++) {
            float v0 = 0.0f, v1 = 0.0f;
            #pragma unroll
            for (int j = 0; j < 4; j++) {
                v0 += sigf(acc[mt][j][0] + b0[j]) + sigf(acc[mt][j][1] + b1v[j]);
                v1 += sigf(acc[mt][j][2] + b0[j]) + sigf(acc[mt][j][3] + b1v[j]);
            }
            v0 += __shfl_xor_sync(0xffffffffu, v0, 1);
            v0 += __shfl_xor_sync(0xffffffffu, v0, 2);
            v1 += __shfl_xor_sync(0xffffffffu, v1, 1);
            v1 += __shfl_xor_sync(0xffffffffu, v1, 2);
            if (qc == 0) {
                atomicAdd(&sScore[mt * 16 + qr], v0);
                atomicAdd(&sScore[mt * 16 + qr + 8], v1);
            }
        }
    }
    __syncthreads();

    // ---- local masked softmax over nr rows ----
    float sv = (tid < nr) ? (mk ? -1e9f : sScore[tid]) : -3.4e38f;

    float m = sv;
    #pragma unroll
    for (int o = 16; o > 0; o >>= 1) m = fmaxf(m, __shfl_xor_sync(0xffffffffu, m, o));
    if (lane == 0) sRed[warp] = m;
    __syncthreads();
    if (warp == 0) {
        float t = (lane < 8) ? sRed[lane] : -3.4e38f;
        #pragma unroll
        for (int o = 16; o > 0; o >>= 1) t = fmaxf(t, __shfl_xor_sync(0xffffffffu, t, o));
        if (lane == 0) sRed[16] = t;
    }
    __syncthreads();
    m = sRed[16];

    const float ev = (tid < nr) ? __expf(sv - m) : 0.0f;
    float l = ev;
    #pragma unroll
    for (int o = 16; o > 0; o >>= 1) l += __shfl_xor_sync(0xffffffffu, l, o);
    if (lane == 0) sRed[warp] = l;
    __syncthreads();
    if (warp == 0) {
        float u = (lane < 8) ? sRed[lane] : 0.0f;
        #pragma unroll
        for (int o = 16; o > 0; o >>= 1) u += __shfl_xor_sync(0xffffffffu, u, o);
        if (lane == 0) sRed[17] = u;
    }
    __syncthreads();                 // sScore reads done; sRed[17] final
    if (tid < nr) sScore[tid] = ev;
    __syncthreads();

    // ---- unnormalized pooled partial from SMEM X (x = hi + lo) ----
    {
        const int cp = tid >> 1, hl = tid & 1;
        const int Cd = (cp >> 3) * 128 + (cp & 3) * 4 + ((cp & 7) >> 2) * 2;
        float accd = 0.0f;
        #pragma unroll 4
        for (int s = 0; s < nr; s++) {
            const int fs = (s >> 4) * 2048 + (s & 7) * 16 + ((s & 15) >> 3);
            const unsigned wh = sw[XH_W + Cd + fs];
            const unsigned wl = sw[XL_W + Cd + fs];
            const float x = (hl ? hf_hi(wh) : hf_lo(wh)) + (hl ? hf_hi(wl) : hf_lo(wl));
            accd += sScore[s] * x;
        }
        g_pp[(size_t)(b * NSPL + fifth) * 256 + tid] = accd;
        if (tid == 0) {
            g_pm[b * NSPL + fifth] = m;
            g_pl[b * NSPL + fifth] = sRed[17];
        }
    }
}

// ---------------------------------------------------------------------------
// K_score: 5 CTAs per batch (m-tiles 3/3/3/2/2 -> rows 0-47/48-95/96-143/
// 144-175/176-207). 50.4 KB smem + <=84 regs -> 3 CTAs/SM.
// ---------------------------------------------------------------------------
__global__ void __launch_bounds__(256, 3)
score_kernel(const float* __restrict__ seq,
             const void*  __restrict__ maskp,
             const float* __restrict__ b1) {
    const int bid = blockIdx.x;
    const int b = bid / NSPL, fifth = bid - NSPL * b;
    if (fifth < 3)       score_body<3>(seq, maskp, b1, b, fifth, fifth * 48);
    else if (fifth == 3) score_body<2>(seq, maskp, b1, b, 3, 144);
    else                 score_body<2>(seq, maskp, b1, b, 4, 176);
}

// ---------------------------------------------------------------------------
// K_combine: merge the 5 fifths -- global max, rescale, normalize.
// ---------------------------------------------------------------------------
__global__ void __launch_bounds__(256)
combine_kernel(float* __restrict__ out) {
    const int b = blockIdx.x, tid = threadIdx.x;
    const int i0 = b * NSPL;
    float m = g_pm[i0];
    #pragma unroll
    for (int j = 1; j < NSPL; j++) m = fmaxf(m, g_pm[i0 + j]);
    float L = 0.0f, p = 0.0f;
    #pragma unroll
    for (int j = 0; j < NSPL; j++) {
        const float w = __expf(g_pm[i0 + j] - m);
        L += w * g_pl[i0 + j];
        p += w * g_pp[(size_t)(i0 + j) * 256 + tid];
    }
    out[(size_t)b * 256 + tid] = p / L;
}

// ---------------------------------------------------------------------------
extern "C" void kernel_launch(void* const* d_in, const int* in_sizes, int n_in,
                              void* d_out, int out_size) {
    const float* cate = (const float*)d_in[0];
    const float* seq  = (const float*)d_in[1];
    const void*  mask = d_in[2];
    const float* W1   = (const float*)d_in[3];
    const float* b1   = (const float*)d_in[4];
    const float* W2   = (const float*)d_in[5];
    const float* b2   = (const float*)d_in[6];
    float*       out  = (float*)d_out;

    cudaFuncSetAttribute(score_kernel,
                         cudaFuncAttributeMaxDynamicSharedMemorySize, SMEM_BYTES);

    prep_kernel<<<258, 256>>>(cate, W2, b2, W1, (const unsigned*)mask);
    score_kernel<<<NSPL * BATCH, 256, SMEM_BYTES>>>(seq, mask, b1);
    combine_kernel<<<BATCH, 256>>>(out);
}

// round 16
// speedup vs baseline: 1.3221x; 1.3221x over previous
#include <cuda_runtime.h>
#include <cuda_fp16.h>
#include <cstdint>

#define BATCH 4096
#define S_SZ  200
#define D_SZ  256
#define NWORK (3 * BATCH)   // (b, third) work items

// ---- K_score dynamic SMEM word map (max NMT=5) ----
#define XH_W     0          // 5*2048 words: X_hi fp16 fragments
#define XL_W     10240      // X_lo fragments
#define SC_W     20480      // 256 f32 combined bias
#define SCORE_W  20736      // 80 f32 row sums / exp values
#define SRED_W   20816      // 20 f32 reduction scratch
#define SMEM_WORDS 20836
#define SMEM_BYTES (SMEM_WORDS * 4)

__device__ float g_catep[BATCH * D_SZ];
__device__ int   g_mask_mode;                 // 0=u8, 1=i32, 2=f32
__device__ uint4 g_w1pk[32 * 16 * 32];        // 256 KB packed fp16 W hi/lo fragments
__device__ float g_pm[BATCH * 3];             // per-third local max
__device__ float g_pl[BATCH * 3];             // per-third local exp-sum
__device__ float g_pp[BATCH * 3 * D_SZ];      // per-third unnormalized pooled partials

__device__ __forceinline__ unsigned pack_hf2(float lo, float hi) {
    unsigned r;
    asm("cvt.rn.f16x2.f32 %0, %1, %2;" : "=r"(r) : "f"(hi), "f"(lo));
    return r;
}
__device__ __forceinline__ float hf_lo(unsigned w) { return __half2float(__ushort_as_half((unsigned short)(w & 0xFFFFu))); }
__device__ __forceinline__ float hf_hi(unsigned w) { return __half2float(__ushort_as_half((unsigned short)(w >> 16))); }
__device__ __forceinline__ float sigf(float x) { return __fdividef(1.0f, 1.0f + __expf(-x)); }

#define MMAF16(d, a0, a1, a2, a3, b0, b1)                                     \
    asm volatile("mma.sync.aligned.m16n8k16.row.col.f32.f16.f16.f32 "         \
                 "{%0,%1,%2,%3}, {%4,%5,%6,%7}, {%8,%9}, {%0,%1,%2,%3};"      \
                 : "+f"(d[0]), "+f"(d[1]), "+f"(d[2]), "+f"(d[3])             \
                 : "r"(a0), "r"(a1), "r"(a2), "r"(a3), "r"(b0), "r"(b1))

// ---------------------------------------------------------------------------
// Prep: blocks 0..255 = catep GEMM (fp32 exact), 256 = W1 fp16 hi/lo fragment
// pack, 257 = mask dtype detection.
// ---------------------------------------------------------------------------
__global__ void prep_kernel(const float* __restrict__ cate,
                            const float* __restrict__ W2,
                            const float* __restrict__ b2,
                            const float* __restrict__ W1,
                            const unsigned* __restrict__ mw) {
    __shared__ float sm[16 * 256];
    __shared__ int   fl[2];
    const int blk = blockIdx.x, tid = threadIdx.x;

    if (blk < 256) {
        const int bbase = blk * 16;
        #pragma unroll
        for (int i = 0; i < 16; i++)
            sm[i * 256 + tid] = cate[(size_t)(bbase + i) * 256 + tid];
        __syncthreads();

        float acc[16];
        #pragma unroll
        for (int r = 0; r < 16; r++) acc[r] = 0.0f;
        const float4* w2row = (const float4*)(W2 + (size_t)tid * 256);
        #pragma unroll 8
        for (int k4 = 0; k4 < 64; k4++) {
            const float4 w = w2row[k4];
            #pragma unroll
            for (int r = 0; r < 16; r++) {
                const float4 s4 = *(const float4*)(sm + r * 256 + k4 * 4);
                acc[r] += s4.x * w.x + s4.y * w.y + s4.z * w.z + s4.w * w.w;
            }
        }
        const float bias = b2[tid];
        #pragma unroll
        for (int r = 0; r < 16; r++)
            g_catep[(size_t)(bbase + r) * 256 + tid] = acc[r] + bias;
    } else if (blk == 256) {
        // entry e = (ntg*16 + kt)*32 + lane ; lane = qr*4 + qc
        for (int e = tid; e < 32 * 16 * 32; e += 256) {
            const int ntg = e >> 9, kt = (e >> 5) & 15, lane = e & 31;
            const int qr = lane >> 2, qc = lane & 3;
            const float* src = W1 + (size_t)(ntg * 8 + qr) * 256 + kt * 16 + 2 * qc;
            const float w0 = src[0], w1v = src[1], w8 = src[8], w9 = src[9];
            const unsigned h0 = pack_hf2(w0, w1v);
            const unsigned h1 = pack_hf2(w8, w9);
            const float2 f0 = __half22float2(*(const __half2*)&h0);
            const float2 f1 = __half22float2(*(const __half2*)&h1);
            const unsigned l0 = pack_hf2(w0 - f0.x, w1v - f0.y);
            const unsigned l1 = pack_hf2(w8 - f1.x, w9 - f1.y);
            g_w1pk[e] = make_uint4(h0, h1, l0, l1);
        }
    } else {
        if (tid == 0) { fl[0] = 0; fl[1] = 0; }
        __syncthreads();
        int lF = 0, lU = 0;
        for (int i = tid; i < 4096; i += 256) {
            const unsigned v = mw[i];
            if (v == 0x3F800000u) lF = 1;
            if (v & 0xFFFFFF00u)  lU = 1;
        }
        if (lF) fl[0] = 1;
        if (lU) fl[1] = 1;
        __syncthreads();
        if (tid == 0) g_mask_mode = fl[0] ? 2 : (fl[1] ? 0 : 1);
    }
}

// ---------------------------------------------------------------------------
// Score body (IDENTICAL to the 928us baseline): direct load + fp16 hi/lo
// split, balanced GEMM (warp = one 32-wide n-strip, all NMT m-tiles), local
// masked softmax + unnormalized pooled partial (flash-style two-level).
// ---------------------------------------------------------------------------
template <int NMT>
__device__ __forceinline__ void score_body(const float* __restrict__ seq,
                                           const void*  __restrict__ maskp,
                                           const float* __restrict__ b1,
                                           int b, int third, int r0) {
    extern __shared__ unsigned sw[];
    const int nr  = NMT * 16;
    const int tid = threadIdx.x, warp = tid >> 5, lane = tid & 31;
    const int qr = lane >> 2, qc = lane & 3;

    float* sC     = (float*)(sw + SC_W);
    float* sScore = (float*)(sw + SCORE_W);
    float* sRed   = (float*)(sw + SRED_W);

    // early mask load (rows >= S_SZ are padding -> masked)
    bool mk = true;
    if (tid < nr) {
        const int s = r0 + tid;
        if (s < S_SZ) {
            const size_t mi = (size_t)b * S_SZ + s;
            const int mode = g_mask_mode;
            if (mode == 0)      mk = ((const unsigned char*)maskp)[mi] != 0;
            else if (mode == 1) mk = ((const int*)maskp)[mi] != 0;
            else                mk = ((const float*)maskp)[mi] != 0.0f;
        }
    }

    sC[tid] = g_catep[(size_t)b * 256 + tid] + b1[tid];
    if (tid < 80) sScore[tid] = 0.0f;
    __syncthreads();

    // ---- P1: load rows [r0, r0+nr) + fp16 hi/lo split, fragment order ----
    {
        const float4* gsrc = (const float4*)(seq + (size_t)b * S_SZ * D_SZ);
        const int nidx = nr * 64;
        for (int idx = tid; idx < nidx; idx += 256) {
            const int lr = idx >> 6, c4 = idx & 63;
            const int g = r0 + lr;
            float4 v = make_float4(0.f, 0.f, 0.f, 0.f);
            if (g < S_SZ) v = gsrc[g * 64 + c4];
            const unsigned h01 = pack_hf2(v.x, v.y);
            const unsigned h23 = pack_hf2(v.z, v.w);
            const float2 f01 = __half22float2(*(const __half2*)&h01);
            const float2 f23 = __half22float2(*(const __half2*)&h23);
            const unsigned l01 = pack_hf2(v.x - f01.x, v.y - f01.y);
            const unsigned l23 = pack_hf2(v.z - f23.x, v.w - f23.y);
            const int cp = 2 * c4, rr = cp & 7;
            const int r16 = lr & 15;
            const int widx = (lr >> 4) * 2048 + (cp >> 3) * 128
                           + (r16 & 7) * 16 + (rr & 3) * 4 + (rr >> 2) * 2 + (r16 >> 3);
            sw[XH_W + widx]     = h01;
            sw[XH_W + widx + 4] = h23;
            sw[XL_W + widx]     = l01;
            sw[XL_W + widx + 4] = l23;
        }
    }
    __syncthreads();

    // ---- P2: balanced GEMM, warp n-strip [warp*32, warp*32+32) ----
    {
        const int n0   = warp * 32;
        const int ntg0 = n0 >> 3;

        float acc[NMT][4][4];
        #pragma unroll
        for (int mt = 0; mt < NMT; mt++)
            #pragma unroll
            for (int j = 0; j < 4; j++)
                #pragma unroll
                for (int i = 0; i < 4; i++) acc[mt][j][i] = 0.0f;

        uint4 wq[4];
        #pragma unroll
        for (int j = 0; j < 4; j++)
            wq[j] = g_w1pk[(size_t)((ntg0 + j) * 16) * 32 + lane];

        #pragma unroll 1
        for (int kt = 0; kt < 16; kt++) {
            uint4 w[4];
            #pragma unroll
            for (int j = 0; j < 4; j++) w[j] = wq[j];
            if (kt < 15) {
                #pragma unroll
                for (int j = 0; j < 4; j++)
                    wq[j] = g_w1pk[(size_t)((ntg0 + j) * 16 + kt + 1) * 32 + lane];
            }
            const unsigned abase = kt * 128 + lane * 4;
            #pragma unroll
            for (int mt = 0; mt < NMT; mt++) {
                const uint4 ah = *(const uint4*)(sw + XH_W + mt * 2048 + abase);
                const uint4 al = *(const uint4*)(sw + XL_W + mt * 2048 + abase);
                #pragma unroll
                for (int j = 0; j < 4; j++)
                    MMAF16(acc[mt][j], ah.x, ah.y, ah.z, ah.w, w[j].x, w[j].y);
                #pragma unroll
                for (int j = 0; j < 4; j++)
                    MMAF16(acc[mt][j], al.x, al.y, al.z, al.w, w[j].x, w[j].y);
                #pragma unroll
                for (int j = 0; j < 4; j++)
                    MMAF16(acc[mt][j], ah.x, ah.y, ah.z, ah.w, w[j].z, w[j].w);
            }
        }

        float b0[4], b1v[4];
        #pragma unroll
        for (int j = 0; j < 4; j++) {
            b0[j]  = sC[n0 + j * 8 + 2 * qc];
            b1v[j] = sC[n0 + j * 8 + 2 * qc + 1];
        }
        #pragma unroll
        for (int mt = 0; mt < NMT; mt++) {
            float v0 = 0.0f, v1 = 0.0f;
            #pragma unroll
            for (int j = 0; j < 4; j++) {
                v0 += sigf(acc[mt][j][0] + b0[j]) + sigf(acc[mt][j][1] + b1v[j]);
                v1 += sigf(acc[mt][j][2] + b0[j]) + sigf(acc[mt][j][3] + b1v[j]);
            }
            v0 += __shfl_xor_sync(0xffffffffu, v0, 1);
            v0 += __shfl_xor_sync(0xffffffffu, v0, 2);
            v1 += __shfl_xor_sync(0xffffffffu, v1, 1);
            v1 += __shfl_xor_sync(0xffffffffu, v1, 2);
            if (qc == 0) {
                atomicAdd(&sScore[mt * 16 + qr], v0);
                atomicAdd(&sScore[mt * 16 + qr + 8], v1);
            }
        }
    }
    __syncthreads();

    // ---- local masked softmax over nr rows ----
    float sv = (tid < nr) ? (mk ? -1e9f : sScore[tid]) : -3.4e38f;

    float m = sv;
    #pragma unroll
    for (int o = 16; o > 0; o >>= 1) m = fmaxf(m, __shfl_xor_sync(0xffffffffu, m, o));
    if (lane == 0) sRed[warp] = m;
    __syncthreads();
    if (warp == 0) {
        float t = (lane < 8) ? sRed[lane] : -3.4e38f;
        #pragma unroll
        for (int o = 16; o > 0; o >>= 1) t = fmaxf(t, __shfl_xor_sync(0xffffffffu, t, o));
        if (lane == 0) sRed[16] = t;
    }
    __syncthreads();
    m = sRed[16];

    const float ev = (tid < nr) ? __expf(sv - m) : 0.0f;
    float l = ev;
    #pragma unroll
    for (int o = 16; o > 0; o >>= 1) l += __shfl_xor_sync(0xffffffffu, l, o);
    if (lane == 0) sRed[warp] = l;
    __syncthreads();
    if (warp == 0) {
        float u = (lane < 8) ? sRed[lane] : 0.0f;
        #pragma unroll
        for (int o = 16; o > 0; o >>= 1) u += __shfl_xor_sync(0xffffffffu, u, o);
        if (lane == 0) sRed[17] = u;
    }
    __syncthreads();                 // sScore reads done; sRed[17] final
    if (tid < nr) sScore[tid] = ev;
    __syncthreads();

    // ---- unnormalized pooled partial from SMEM X (x = hi + lo) ----
    {
        const int cp = tid >> 1, hl = tid & 1;
        const int Cd = (cp >> 3) * 128 + (cp & 3) * 4 + ((cp & 7) >> 2) * 2;
        float accd = 0.0f;
        #pragma unroll 4
        for (int s = 0; s < nr; s++) {
            const int fs = (s >> 4) * 2048 + (s & 7) * 16 + ((s & 15) >> 3);
            const unsigned wh = sw[XH_W + Cd + fs];
            const unsigned wl = sw[XL_W + Cd + fs];
            const float x = (hl ? hf_hi(wh) : hf_lo(wh)) + (hl ? hf_hi(wl) : hf_lo(wl));
            accd += sScore[s] * x;
        }
        g_pp[(size_t)(b * 3 + third) * 256 + tid] = accd;
        if (tid == 0) {
            g_pm[b * 3 + third] = m;
            g_pl[b * 3 + third] = sRed[17];
        }
    }
}

// ---------------------------------------------------------------------------
// K_score: PERSISTENT. grid = 2 x numSMs; each CTA strides over the 12288
// (b, third) items. Co-resident CTAs drift out of phase, so one CTA's
// load/epilogue hides under the other's MMA stream.
// ---------------------------------------------------------------------------
__global__ void __launch_bounds__(256, 2)
score_kernel(const float* __restrict__ seq,
             const void*  __restrict__ maskp,
             const float* __restrict__ b1) {
    for (int item = blockIdx.x; item < NWORK; item += gridDim.x) {
        const int b = item / 3, third = item - 3 * b;
        if (third == 0)      score_body<5>(seq, maskp, b1, b, 0, 0);
        else if (third == 1) score_body<4>(seq, maskp, b1, b, 1, 80);
        else                 score_body<4>(seq, maskp, b1, b, 2, 144);
        __syncthreads();     // P4 smem reads before next item's P1 writes
    }
}

// ---------------------------------------------------------------------------
// K_combine: merge the 3 thirds -- global max, rescale, normalize.
// ---------------------------------------------------------------------------
__global__ void __launch_bounds__(256)
combine_kernel(float* __restrict__ out) {
    const int b = blockIdx.x, tid = threadIdx.x;
    const float m0 = g_pm[b * 3], m1 = g_pm[b * 3 + 1], m2 = g_pm[b * 3 + 2];
    const float m  = fmaxf(m0, fmaxf(m1, m2));
    const float w0 = __expf(m0 - m), w1 = __expf(m1 - m), w2 = __expf(m2 - m);
    const float L  = w0 * g_pl[b * 3] + w1 * g_pl[b * 3 + 1] + w2 * g_pl[b * 3 + 2];
    const float inv = 1.0f / L;
    const float p = w0 * g_pp[(size_t)(b * 3) * 256 + tid]
                  + w1 * g_pp[(size_t)(b * 3 + 1) * 256 + tid]
                  + w2 * g_pp[(size_t)(b * 3 + 2) * 256 + tid];
    out[(size_t)b * 256 + tid] = p * inv;
}

// ---------------------------------------------------------------------------
extern "C" void kernel_launch(void* const* d_in, const int* in_sizes, int n_in,
                              void* d_out, int out_size) {
    const float* cate = (const float*)d_in[0];
    const float* seq  = (const float*)d_in[1];
    const void*  mask = d_in[2];
    const float* W1   = (const float*)d_in[3];
    const float* b1   = (const float*)d_in[4];
    const float* W2   = (const float*)d_in[5];
    const float* b2   = (const float*)d_in[6];
    float*       out  = (float*)d_out;

    int nsm = 148;
    cudaDeviceGetAttribute(&nsm, cudaDevAttrMultiProcessorCount, 0);

    cudaFuncSetAttribute(score_kernel,
                         cudaFuncAttributeMaxDynamicSharedMemorySize, SMEM_BYTES);

    prep_kernel<<<258, 256>>>(cate, W2, b2, W1, (const unsigned*)mask);
    score_kernel<<<2 * nsm, 256, SMEM_BYTES>>>(seq, mask, b1);
    combine_kernel<<<BATCH, 256>>>(out);
}

// round 17
// speedup vs baseline: 1.3941x; 1.0545x over previous
#include <cuda_runtime.h>
#include <cuda_fp16.h>
#include <cstdint>

#define BATCH 4096
#define S_SZ  200
#define D_SZ  256

// ---- K_score dynamic SMEM word map (max NMT=5) ----
#define XH_W     0          // 5*2048 words: X_hi fp16 fragments
#define XL_W     10240      // X_lo fragments
#define SC_W     20480      // 256 f32 combined bias
#define SCORE_W  20736      // 80 f32 row sums / exp values
#define SRED_W   20816      // 20 f32 reduction scratch
#define SMEM_WORDS 20836
#define SMEM_BYTES (SMEM_WORDS * 4)

__device__ float g_catep[BATCH * D_SZ];       // cate@W2^T + b2 + b1 (combined bias)
__device__ float g_w2t[D_SZ * D_SZ];          // W2 transposed: [k][e]
__device__ int   g_mask_mode;                 // 0=u8, 1=i32, 2=f32
__device__ uint4 g_w1pk[32 * 16 * 32];        // 256 KB packed fp16 W hi/lo fragments
__device__ float g_pm[BATCH * 3];             // per-third local max
__device__ float g_pl[BATCH * 3];             // per-third local exp-sum
__device__ float g_pp[BATCH * 3 * D_SZ];      // per-third unnormalized pooled partials

__device__ __forceinline__ unsigned pack_hf2(float lo, float hi) {
    unsigned r;
    asm("cvt.rn.f16x2.f32 %0, %1, %2;" : "=r"(r) : "f"(hi), "f"(lo));
    return r;
}
__device__ __forceinline__ float hf_lo(unsigned w) { return __half2float(__ushort_as_half((unsigned short)(w & 0xFFFFu))); }
__device__ __forceinline__ float hf_hi(unsigned w) { return __half2float(__ushort_as_half((unsigned short)(w >> 16))); }
__device__ __forceinline__ float sigf(float x) { return __fdividef(1.0f, 1.0f + __expf(-x)); }

#define MMAF16(d, a0, a1, a2, a3, b0, b1)                                     \
    asm volatile("mma.sync.aligned.m16n8k16.row.col.f32.f16.f16.f32 "         \
                 "{%0,%1,%2,%3}, {%4,%5,%6,%7}, {%8,%9}, {%0,%1,%2,%3};"      \
                 : "+f"(d[0]), "+f"(d[1]), "+f"(d[2]), "+f"(d[3])             \
                 : "r"(a0), "r"(a1), "r"(a2), "r"(a3), "r"(b0), "r"(b1))

// ---------------------------------------------------------------------------
// prep0: blocks 0..63 = W2 transpose (32x32 smem tiles, coalesced both ways),
//        blocks 64..71 = W1 fp16 hi/lo fragment pack (spread over 8 blocks),
//        block 72 = mask dtype detection.
// ---------------------------------------------------------------------------
__global__ void prep0_kernel(const float* __restrict__ W2,
                             const float* __restrict__ W1,
                             const unsigned* __restrict__ mw) {
    __shared__ float t[32][33];
    __shared__ int   fl[2];
    const int blk = blockIdx.x, tid = threadIdx.x;

    if (blk < 64) {
        // tile (te, tk): rows e in [te*32, ..), cols k in [tk*32, ..)
        const int te = blk >> 3, tk = blk & 7;
        const int tx = tid & 31, ty = tid >> 5;          // 8 rows per pass
        #pragma unroll
        for (int i = 0; i < 4; i++) {
            const int e = te * 32 + ty + i * 8;
            t[ty + i * 8][tx] = W2[(size_t)e * 256 + tk * 32 + tx];
        }
        __syncthreads();
        #pragma unroll
        for (int i = 0; i < 4; i++) {
            const int k = tk * 32 + ty + i * 8;
            g_w2t[(size_t)k * 256 + te * 32 + tx] = t[tx][ty + i * 8];
        }
    } else if (blk < 72) {
        // entry e = (ntg*16 + kt)*32 + lane ; lane = qr*4 + qc
        const int base = (blk - 64) * 2048;
        for (int e = base + tid; e < base + 2048; e += 256) {
            const int ntg = e >> 9, kt = (e >> 5) & 15, lane = e & 31;
            const int qr = lane >> 2, qc = lane & 3;
            const float* src = W1 + (size_t)(ntg * 8 + qr) * 256 + kt * 16 + 2 * qc;
            const float w0 = src[0], w1v = src[1], w8 = src[8], w9 = src[9];
            const unsigned h0 = pack_hf2(w0, w1v);
            const unsigned h1 = pack_hf2(w8, w9);
            const float2 f0 = __half22float2(*(const __half2*)&h0);
            const float2 f1 = __half22float2(*(const __half2*)&h1);
            const unsigned l0 = pack_hf2(w0 - f0.x, w1v - f0.y);
            const unsigned l1 = pack_hf2(w8 - f1.x, w9 - f1.y);
            g_w1pk[e] = make_uint4(h0, h1, l0, l1);
        }
    } else {
        if (tid == 0) { fl[0] = 0; fl[1] = 0; }
        __syncthreads();
        int lF = 0, lU = 0;
        for (int i = tid; i < 4096; i += 256) {
            const unsigned v = mw[i];
            if (v == 0x3F800000u) lF = 1;
            if (v & 0xFFFFFF00u)  lU = 1;
        }
        if (lF) fl[0] = 1;
        if (lU) fl[1] = 1;
        __syncthreads();
        if (tid == 0) g_mask_mode = fl[0] ? 2 : (fl[1] ? 0 : 1);
    }
}

// ---------------------------------------------------------------------------
// prep1: catep GEMM (fp32 exact) reading g_w2t coalesced; folds b2 AND b1
// into g_catep so score_kernel reads a single combined bias array.
// ---------------------------------------------------------------------------
__global__ void prep1_kernel(const float* __restrict__ cate,
                             const float* __restrict__ b2,
                             const float* __restrict__ b1) {
    __shared__ float sm[16 * 256];
    const int bbase = blockIdx.x * 16;
    const int tid = threadIdx.x;

    #pragma unroll
    for (int i = 0; i < 16; i++)
        sm[i * 256 + tid] = cate[(size_t)(bbase + i) * 256 + tid];
    __syncthreads();

    float acc[16];
    #pragma unroll
    for (int r = 0; r < 16; r++) acc[r] = 0.0f;

    #pragma unroll 4
    for (int k = 0; k < 256; k++) {
        const float w = g_w2t[(size_t)k * 256 + tid];   // coalesced
        #pragma unroll
        for (int r = 0; r < 16; r++) acc[r] += sm[r * 256 + k] * w;  // broadcast LDS
    }
    const float bias = b2[tid] + b1[tid];
    #pragma unroll
    for (int r = 0; r < 16; r++)
        g_catep[(size_t)(bbase + r) * 256 + tid] = acc[r] + bias;
}

// ---------------------------------------------------------------------------
// Score body (IDENTICAL to the 928us baseline except sC reads the pre-folded
// bias): direct load + fp16 hi/lo split, balanced GEMM (warp = one 32-wide
// n-strip, all NMT m-tiles), local masked softmax + unnormalized pooled
// partial (flash-style two-level softmax).
// ---------------------------------------------------------------------------
template <int NMT>
__device__ __forceinline__ void score_body(const float* __restrict__ seq,
                                           const void*  __restrict__ maskp,
                                           int b, int third, int r0) {
    extern __shared__ unsigned sw[];
    const int nr  = NMT * 16;
    const int tid = threadIdx.x, warp = tid >> 5, lane = tid & 31;
    const int qr = lane >> 2, qc = lane & 3;

    float* sC     = (float*)(sw + SC_W);
    float* sScore = (float*)(sw + SCORE_W);
    float* sRed   = (float*)(sw + SRED_W);

    // early mask load (rows >= S_SZ are padding -> masked)
    bool mk = true;
    if (tid < nr) {
        const int s = r0 + tid;
        if (s < S_SZ) {
            const size_t mi = (size_t)b * S_SZ + s;
            const int mode = g_mask_mode;
            if (mode == 0)      mk = ((const unsigned char*)maskp)[mi] != 0;
            else if (mode == 1) mk = ((const int*)maskp)[mi] != 0;
            else                mk = ((const float*)maskp)[mi] != 0.0f;
        }
    }

    sC[tid] = g_catep[(size_t)b * 256 + tid];
    if (tid < 80) sScore[tid] = 0.0f;
    __syncthreads();

    // ---- P1: load rows [r0, r0+nr) + fp16 hi/lo split, fragment order ----
    {
        const float4* gsrc = (const float4*)(seq + (size_t)b * S_SZ * D_SZ);
        const int nidx = nr * 64;
        for (int idx = tid; idx < nidx; idx += 256) {
            const int lr = idx >> 6, c4 = idx & 63;
            const int g = r0 + lr;
            float4 v = make_float4(0.f, 0.f, 0.f, 0.f);
            if (g < S_SZ) v = gsrc[g * 64 + c4];
            const unsigned h01 = pack_hf2(v.x, v.y);
            const unsigned h23 = pack_hf2(v.z, v.w);
            const float2 f01 = __half22float2(*(const __half2*)&h01);
            const float2 f23 = __half22float2(*(const __half2*)&h23);
            const unsigned l01 = pack_hf2(v.x - f01.x, v.y - f01.y);
            const unsigned l23 = pack_hf2(v.z - f23.x, v.w - f23.y);
            const int cp = 2 * c4, rr = cp & 7;
            const int r16 = lr & 15;
            const int widx = (lr >> 4) * 2048 + (cp >> 3) * 128
                           + (r16 & 7) * 16 + (rr & 3) * 4 + (rr >> 2) * 2 + (r16 >> 3);
            sw[XH_W + widx]     = h01;
            sw[XH_W + widx + 4] = h23;
            sw[XL_W + widx]     = l01;
            sw[XL_W + widx + 4] = l23;
        }
    }
    __syncthreads();

    // ---- P2: balanced GEMM, warp n-strip [warp*32, warp*32+32) ----
    {
        const int n0   = warp * 32;
        const int ntg0 = n0 >> 3;

        float acc[NMT][4][4];
        #pragma unroll
        for (int mt = 0; mt < NMT; mt++)
            #pragma unroll
            for (int j = 0; j < 4; j++)
                #pragma unroll
                for (int i = 0; i < 4; i++) acc[mt][j][i] = 0.0f;

        uint4 wq[4];
        #pragma unroll
        for (int j = 0; j < 4; j++)
            wq[j] = g_w1pk[(size_t)((ntg0 + j) * 16) * 32 + lane];

        #pragma unroll 1
        for (int kt = 0; kt < 16; kt++) {
            uint4 w[4];
            #pragma unroll
            for (int j = 0; j < 4; j++) w[j] = wq[j];
            if (kt < 15) {
                #pragma unroll
                for (int j = 0; j < 4; j++)
                    wq[j] = g_w1pk[(size_t)((ntg0 + j) * 16 + kt + 1) * 32 + lane];
            }
            const unsigned abase = kt * 128 + lane * 4;
            #pragma unroll
            for (int mt = 0; mt < NMT; mt++) {
                const uint4 ah = *(const uint4*)(sw + XH_W + mt * 2048 + abase);
                const uint4 al = *(const uint4*)(sw + XL_W + mt * 2048 + abase);
                #pragma unroll
                for (int j = 0; j < 4; j++)
                    MMAF16(acc[mt][j], ah.x, ah.y, ah.z, ah.w, w[j].x, w[j].y);
                #pragma unroll
                for (int j = 0; j < 4; j++)
                    MMAF16(acc[mt][j], al.x, al.y, al.z, al.w, w[j].x, w[j].y);
                #pragma unroll
                for (int j = 0; j < 4; j++)
                    MMAF16(acc[mt][j], ah.x, ah.y, ah.z, ah.w, w[j].z, w[j].w);
            }
        }

        float b0[4], b1v[4];
        #pragma unroll
        for (int j = 0; j < 4; j++) {
            b0[j]  = sC[n0 + j * 8 + 2 * qc];
            b1v[j] = sC[n0 + j * 8 + 2 * qc + 1];
        }
        #pragma unroll
        for (int mt = 0; mt < NMT; mt++) {
            float v0 = 0.0f, v1 = 0.0f;
            #pragma unroll
            for (int j = 0; j < 4; j++) {
                v0 += sigf(acc[mt][j][0] + b0[j]) + sigf(acc[mt][j][1] + b1v[j]);
                v1 += sigf(acc[mt][j][2] + b0[j]) + sigf(acc[mt][j][3] + b1v[j]);
            }
            v0 += __shfl_xor_sync(0xffffffffu, v0, 1);
            v0 += __shfl_xor_sync(0xffffffffu, v0, 2);
            v1 += __shfl_xor_sync(0xffffffffu, v1, 1);
            v1 += __shfl_xor_sync(0xffffffffu, v1, 2);
            if (qc == 0) {
                atomicAdd(&sScore[mt * 16 + qr], v0);
                atomicAdd(&sScore[mt * 16 + qr + 8], v1);
            }
        }
    }
    __syncthreads();

    // ---- local masked softmax over nr rows ----
    float sv = (tid < nr) ? (mk ? -1e9f : sScore[tid]) : -3.4e38f;

    float m = sv;
    #pragma unroll
    for (int o = 16; o > 0; o >>= 1) m = fmaxf(m, __shfl_xor_sync(0xffffffffu, m, o));
    if (lane == 0) sRed[warp] = m;
    __syncthreads();
    if (warp == 0) {
        float t = (lane < 8) ? sRed[lane] : -3.4e38f;
        #pragma unroll
        for (int o = 16; o > 0; o >>= 1) t = fmaxf(t, __shfl_xor_sync(0xffffffffu, t, o));
        if (lane == 0) sRed[16] = t;
    }
    __syncthreads();
    m = sRed[16];

    const float ev = (tid < nr) ? __expf(sv - m) : 0.0f;
    float l = ev;
    #pragma unroll
    for (int o = 16; o > 0; o >>= 1) l += __shfl_xor_sync(0xffffffffu, l, o);
    if (lane == 0) sRed[warp] = l;
    __syncthreads();
    if (warp == 0) {
        float u = (lane < 8) ? sRed[lane] : 0.0f;
        #pragma unroll
        for (int o = 16; o > 0; o >>= 1) u += __shfl_xor_sync(0xffffffffu, u, o);
        if (lane == 0) sRed[17] = u;
    }
    __syncthreads();                 // sScore reads done; sRed[17] final
    if (tid < nr) sScore[tid] = ev;
    __syncthreads();

    // ---- unnormalized pooled partial from SMEM X (x = hi + lo) ----
    {
        const int cp = tid >> 1, hl = tid & 1;
        const int Cd = (cp >> 3) * 128 + (cp & 3) * 4 + ((cp & 7) >> 2) * 2;
        float accd = 0.0f;
        #pragma unroll 4
        for (int s = 0; s < nr; s++) {
            const int fs = (s >> 4) * 2048 + (s & 7) * 16 + ((s & 15) >> 3);
            const unsigned wh = sw[XH_W + Cd + fs];
            const unsigned wl = sw[XL_W + Cd + fs];
            const float x = (hl ? hf_hi(wh) : hf_lo(wh)) + (hl ? hf_hi(wl) : hf_lo(wl));
            accd += sScore[s] * x;
        }
        g_pp[(size_t)(b * 3 + third) * 256 + tid] = accd;
        if (tid == 0) {
            g_pm[b * 3 + third] = m;
            g_pl[b * 3 + third] = sRed[17];
        }
    }
}

// ---------------------------------------------------------------------------
// K_score: 3 CTAs per batch (rows 0-79 / 80-143 / 144-207).
// 81 KB smem, 2 CTAs/SM; scheduler back-fill provides cross-CTA overlap.
// ---------------------------------------------------------------------------
__global__ void __launch_bounds__(256, 2)
score_kernel(const float* __restrict__ seq,
             const void*  __restrict__ maskp) {
    const int bid = blockIdx.x;
    const int b = bid / 3, third = bid - 3 * b;
    if (third == 0)      score_body<5>(seq, maskp, b, 0, 0);
    else if (third == 1) score_body<4>(seq, maskp, b, 1, 80);
    else                 score_body<4>(seq, maskp, b, 2, 144);
}

// ---------------------------------------------------------------------------
// K_combine: merge the 3 thirds -- global max, rescale, normalize.
// ---------------------------------------------------------------------------
__global__ void __launch_bounds__(256)
combine_kernel(float* __restrict__ out) {
    const int b = blockIdx.x, tid = threadIdx.x;
    const float m0 = g_pm[b * 3], m1 = g_pm[b * 3 + 1], m2 = g_pm[b * 3 + 2];
    const float m  = fmaxf(m0, fmaxf(m1, m2));
    const float w0 = __expf(m0 - m), w1 = __expf(m1 - m), w2 = __expf(m2 - m);
    const float L  = w0 * g_pl[b * 3] + w1 * g_pl[b * 3 + 1] + w2 * g_pl[b * 3 + 2];
    const float inv = 1.0f / L;
    const float p = w0 * g_pp[(size_t)(b * 3) * 256 + tid]
                  + w1 * g_pp[(size_t)(b * 3 + 1) * 256 + tid]
                  + w2 * g_pp[(size_t)(b * 3 + 2) * 256 + tid];
    out[(size_t)b * 256 + tid] = p * inv;
}

// ---------------------------------------------------------------------------
extern "C" void kernel_launch(void* const* d_in, const int* in_sizes, int n_in,
                              void* d_out, int out_size) {
    const float* cate = (const float*)d_in[0];
    const float* seq  = (const float*)d_in[1];
    const void*  mask = d_in[2];
    const float* W1   = (const float*)d_in[3];
    const float* b1   = (const float*)d_in[4];
    const float* W2   = (const float*)d_in[5];
    const float* b2   = (const float*)d_in[6];
    float*       out  = (float*)d_out;

    cudaFuncSetAttribute(score_kernel,
                         cudaFuncAttributeMaxDynamicSharedMemorySize, SMEM_BYTES);

    prep0_kernel<<<73, 256>>>(W2, W1, (const unsigned*)mask);
    prep1_kernel<<<256, 256>>>(cate, b2, b1);
    score_kernel<<<3 * BATCH, 256, SMEM_BYTES>>>(seq, mask);
    combine_kernel<<<BATCH, 256>>>(out);
}